// round 8
// baseline (speedup 1.0000x reference)
#include <cuda_runtime.h>
#include <cuda_fp16.h>

// ---------------------------------------------------------------------------
// ESN recurrence, fp16 tensor-core, round 8.
//  vs R7: no monolithic group barrier. Each producer CTA has a padded
//  monotone flag (red.release once/step). Consumer warps process their
//  K-quarter as 4 chunks of 4 kc, acquiring the matching producer flag per
//  chunk (own CTA's chunk needs no wait). Detection overlaps mma drain.
// ---------------------------------------------------------------------------

#define TT     2048
#define BB     256
#define HH     1024
#define DD     128
#define NCTA   128
#define THREADS 512
#define KC2T   36
#define KEEP0  2028
#define NLAST  20
#define KOUT   (NLAST*HH)

#define SMEM_W_BYTES   (8*KC2T*32*16)    // 147456
#define SMEM_RED_BYTES (8*3*2*32*16)     // 24576
#define SMEM_TOTAL     (SMEM_W_BYTES + SMEM_RED_BYTES)

// ---- device globals --------------------------------------------------------
__device__ __align__(16) uint4 g_X[(size_t)TT*16*8*32];
__device__ __align__(16) uint4 g_W[128*KC2T*32];
__device__ __align__(16) uint4 g_H[2][16][64][32];
__device__ float    g_hist[(size_t)NLAST*BB*HH];
__device__ unsigned g_pflag[8*16*32];    // [group 8][producer 16], 128B apart

// ---- helpers ---------------------------------------------------------------
__device__ __forceinline__ unsigned pkh(float a, float b) {
    __half2 t = __floats2half2_rn(a, b);
    return reinterpret_cast<unsigned&>(t);
}
__device__ __forceinline__ void mma16816(float* c, const uint4 a, const uint2 b) {
    asm volatile(
        "mma.sync.aligned.m16n8k16.row.col.f32.f16.f16.f32 "
        "{%0,%1,%2,%3}, {%4,%5,%6,%7}, {%8,%9}, {%0,%1,%2,%3};\n"
        : "+f"(c[0]), "+f"(c[1]), "+f"(c[2]), "+f"(c[3])
        : "r"(a.x), "r"(a.y), "r"(a.z), "r"(a.w), "r"(b.x), "r"(b.y));
}

// 2-m16 span over CNT kc-pairs, ring depth 2. c layout: [m 2][n 2][4].
template<int CNT>
__device__ __forceinline__ void mma_span2(float* c,
        const uint4* __restrict__ A0, const uint4* __restrict__ A1,
        const uint4* __restrict__ sW4, int n8a, int n8b, int kc2base, int lane) {
    uint4 ra[2][4];
#pragma unroll
    for (int i = 0; i < 2 && i < CNT; i++) {
        ra[i][0] = __ldcg(A0 + (size_t)(2*i)   * 32);
        ra[i][1] = __ldcg(A0 + (size_t)(2*i+1) * 32);
        ra[i][2] = __ldcg(A1 + (size_t)(2*i)   * 32);
        ra[i][3] = __ldcg(A1 + (size_t)(2*i+1) * 32);
    }
#pragma unroll
    for (int j = 0; j < CNT; j++) {
        uint4 b0 = sW4[(size_t)(n8a*KC2T + kc2base + j)*32 + lane];
        uint4 b1 = sW4[(size_t)(n8b*KC2T + kc2base + j)*32 + lane];
        uint4 a00 = ra[j&1][0], a01 = ra[j&1][1];
        uint4 a10 = ra[j&1][2], a11 = ra[j&1][3];
        if (j + 2 < CNT) {
            ra[j&1][0] = __ldcg(A0 + (size_t)(2*(j+2))   * 32);
            ra[j&1][1] = __ldcg(A0 + (size_t)(2*(j+2)+1) * 32);
            ra[j&1][2] = __ldcg(A1 + (size_t)(2*(j+2))   * 32);
            ra[j&1][3] = __ldcg(A1 + (size_t)(2*(j+2)+1) * 32);
        }
        mma16816(c + 0,  a00, make_uint2(b0.x, b0.y));
        mma16816(c + 0,  a01, make_uint2(b0.z, b0.w));
        mma16816(c + 4,  a00, make_uint2(b1.x, b1.y));
        mma16816(c + 4,  a01, make_uint2(b1.z, b1.w));
        mma16816(c + 8,  a10, make_uint2(b0.x, b0.y));
        mma16816(c + 8,  a11, make_uint2(b0.z, b0.w));
        mma16816(c + 12, a10, make_uint2(b1.x, b1.y));
        mma16816(c + 12, a11, make_uint2(b1.z, b1.w));
    }
}

// ---- prep kernels ----------------------------------------------------------
__global__ void prep_zero() {
    for (int i = threadIdx.x; i < 8 * 16 * 32; i += blockDim.x) g_pflag[i] = 0u;
}

__global__ void prep_w(const float* __restrict__ w_r, const float* __restrict__ w_in) {
    int i = blockIdx.x * blockDim.x + threadIdx.x;
    if (i >= 128 * KC2T * 32) return;
    int lane = i & 31;
    int kc2  = (i >> 5) % KC2T;
    int n8   = i / (KC2T * 32);
    int n    = n8 * 8 + (lane >> 2);
    unsigned u[4];
#pragma unroll
    for (int s = 0; s < 2; s++) {
        int kc = 2 * kc2 + s;
        int k0 = kc * 16 + (lane & 3) * 2;
        float v[4];
#pragma unroll
        for (int r = 0; r < 4; r++) {
            int k = k0 + ((r >> 1) * 8) + (r & 1);
            v[r] = (k < HH) ? w_r[(size_t)k * HH + n] : w_in[(size_t)(k - HH) * HH + n];
        }
        u[2*s + 0] = pkh(v[0], v[1]);
        u[2*s + 1] = pkh(v[2], v[3]);
    }
    g_W[i] = make_uint4(u[0], u[1], u[2], u[3]);
}

__global__ void prep_x(const float* __restrict__ x) {
    size_t i = (size_t)blockIdx.x * blockDim.x + threadIdx.x;
    if (i >= (size_t)TT * 16 * 8 * 32) return;
    int lane = (int)(i & 31);
    int kcx  = (int)((i >> 5) & 7);
    int m16  = (int)((i >> 8) & 15);
    int t    = (int)(i >> 12);
    int b = m16 * 16 + (lane >> 2);
    int d = kcx * 16 + (lane & 3) * 2;
    const float* p0 = x + ((size_t)b * TT + t) * DD + d;
    const float* p1 = p0 + (size_t)8 * TT * DD;
    float2 a0 = *(const float2*)(p0);
    float2 a1 = *(const float2*)(p1);
    float2 a2 = *(const float2*)(p0 + 8);
    float2 a3 = *(const float2*)(p1 + 8);
    g_X[i] = make_uint4(pkh(a0.x, a0.y), pkh(a1.x, a1.y),
                        pkh(a2.x, a2.y), pkh(a3.x, a3.y));
}

// ---- main persistent kernel ------------------------------------------------
__global__ void __launch_bounds__(THREADS, 1) esn_main() {
    extern __shared__ __align__(16) unsigned char smem[];
    uint4*  sW4  = reinterpret_cast<uint4*>(smem);
    float4* sred = reinterpret_cast<float4*>(smem + SMEM_W_BYTES);

    const int tid   = threadIdx.x;
    const int lane  = tid & 31;
    const int warp  = tid >> 5;
    const int wn    = warp & 3;          // n-pair
    const int wq    = warp >> 2;         // K-quarter 0..3
    const int cta_n = blockIdx.x & 15;   // producer index within group
    const int cta_m = blockIdx.x >> 4;   // 8 independent groups
    const int m16g0 = 2 * cta_m;
    const int m16g1 = m16g0 + 1;
    const int n8a   = 2 * wn;
    const int n8b   = 2 * wn + 1;
    const bool owner = (wq < 2);
    const int m16o  = m16g0 + wq;
    const int kcw   = 4 * cta_n + wn;

    {
        const uint4* src = g_W + (size_t)(8 * cta_n) * KC2T * 32;
        for (int i = tid; i < 8 * KC2T * 32; i += THREADS) sW4[i] = src[i];
    }
    __syncthreads();

    float hprev[8];
    unsigned* const myflag = &g_pflag[(cta_m * 16 + cta_n) * 32];
    // flags of the 4 producers feeding this warp's K-quarter
    unsigned* const qflag  = &g_pflag[(cta_m * 16 + 4 * wq) * 32];

    for (int t = 0; t < TT; t++) {
        float c[16];
#pragma unroll
        for (int i = 0; i < 16; i++) c[i] = 0.f;

        // pre-wait: this quarter's x kc-pair
        {
            const uint4* X0 = &g_X[(((size_t)t * 16 + m16g0) * 8 + 2 * wq) * 32 + lane];
            const uint4* X1 = &g_X[(((size_t)t * 16 + m16g1) * 8 + 2 * wq) * 32 + lane];
            mma_span2<1>(c, X0, X1, sW4, n8a, n8b, 32 + wq, lane);
        }

        if (t > 0) {
            const int rb = t & 1;
            // process 4 chunks of 4 kc; start at own CTA's chunk if in range
#pragma unroll
            for (int i = 0; i < 4; i++) {
                int p = 4 * wq + i;               // producer CTA index
                if (p != cta_n) {
                    unsigned v;
                    do {
                        asm volatile("ld.acquire.gpu.global.u32 %0, [%1];"
                                     : "=r"(v) : "l"(qflag + i * 32) : "memory");
                    } while (v < (unsigned)t);
                }
                const uint4* A0 = &g_H[rb][m16g0][16 * wq + 4 * i][lane];
                const uint4* A1 = &g_H[rb][m16g1][16 * wq + 4 * i][lane];
                mma_span2<2>(c, A0, A1, sW4, n8a, n8b, 8 * wq + 2 * i, lane);
            }
        }

        // 4-way K reduction through smem.
#pragma unroll
        for (int mi = 0; mi < 2; mi++) {
            if (wq != mi) {
                int src = wq - (wq > mi ? 1 : 0);
                int base = (((mi * 4 + wn) * 3 + src) * 2) * 32 + lane;
                const float* p = c + mi * 8;
                sred[base]      = make_float4(p[0], p[1], p[2], p[3]);
                sred[base + 32] = make_float4(p[4], p[5], p[6], p[7]);
            }
        }
        __syncthreads();

        float hv[8];
        if (owner) {
            float fin[8];
            const float* cm = c + wq * 8;
#pragma unroll
            for (int i = 0; i < 8; i++) fin[i] = cm[i];
#pragma unroll
            for (int src = 0; src < 3; src++) {
                int base = (((wq * 4 + wn) * 3 + src) * 2) * 32 + lane;
                float4 r0 = sred[base];
                float4 r1 = sred[base + 32];
                fin[0] += r0.x; fin[1] += r0.y; fin[2] += r0.z; fin[3] += r0.w;
                fin[4] += r1.x; fin[5] += r1.y; fin[6] += r1.z; fin[7] += r1.w;
            }

            if (t == 0) {
#pragma unroll
                for (int i = 0; i < 8; i++) hv[i] = tanhf(fin[i]);
            } else {
#pragma unroll
                for (int i = 0; i < 8; i++) hv[i] = 0.1f * hprev[i] + 0.9f * tanhf(fin[i]);
            }
#pragma unroll
            for (int i = 0; i < 8; i++) hprev[i] = hv[i];

            uint4 nh = make_uint4(pkh(hv[0], hv[1]), pkh(hv[2], hv[3]),
                                  pkh(hv[4], hv[5]), pkh(hv[6], hv[7]));
            __stcg(&g_H[(t + 1) & 1][m16o][kcw][lane], nh);
        }

        // all owner stores done -> bump own producer flag
        if (t < TT - 1) {
            __syncthreads();
            if (tid == 0)
                asm volatile("red.release.gpu.global.add.u32 [%0], %1;"
                             :: "l"(myflag), "r"(1u) : "memory");
        }

        if (owner && t >= KEEP0) {
            int r0r = m16o * 16 + (lane >> 2);
            int cb  = kcw * 16 + (lane & 3) * 2;
            size_t base = (size_t)(t - KEEP0) * BB * HH;
            *(float2*)&g_hist[base + (size_t)(r0r)     * HH + cb]     = make_float2(hv[0], hv[1]);
            *(float2*)&g_hist[base + (size_t)(r0r + 8) * HH + cb]     = make_float2(hv[2], hv[3]);
            *(float2*)&g_hist[base + (size_t)(r0r)     * HH + cb + 8] = make_float2(hv[4], hv[5]);
            *(float2*)&g_hist[base + (size_t)(r0r + 8) * HH + cb + 8] = make_float2(hv[6], hv[7]);
        }
    }
}

// ---- readout ---------------------------------------------------------------
__global__ void readout(const float* __restrict__ lw, const float* __restrict__ lb,
                        float* __restrict__ out) {
    int b    = blockIdx.x;
    int warp = threadIdx.x >> 5;
    int lane = threadIdx.x & 31;
    int o0   = warp * 4;
    float a0 = 0.f, a1 = 0.f, a2 = 0.f, a3 = 0.f;
    for (int k = lane; k < KOUT; k += 32) {
        int s = k >> 10, j = k & (HH - 1);
        float hval = g_hist[(size_t)s * BB * HH + (size_t)b * HH + j];
        a0 += hval * __ldg(&lw[(size_t)(o0 + 0) * KOUT + k]);
        a1 += hval * __ldg(&lw[(size_t)(o0 + 1) * KOUT + k]);
        a2 += hval * __ldg(&lw[(size_t)(o0 + 2) * KOUT + k]);
        a3 += hval * __ldg(&lw[(size_t)(o0 + 3) * KOUT + k]);
    }
#pragma unroll
    for (int off = 16; off > 0; off >>= 1) {
        a0 += __shfl_down_sync(0xffffffffu, a0, off);
        a1 += __shfl_down_sync(0xffffffffu, a1, off);
        a2 += __shfl_down_sync(0xffffffffu, a2, off);
        a3 += __shfl_down_sync(0xffffffffu, a3, off);
    }
    if (lane == 0) {
        out[b * 32 + o0 + 0] = a0 + lb[o0 + 0];
        out[b * 32 + o0 + 1] = a1 + lb[o0 + 1];
        out[b * 32 + o0 + 2] = a2 + lb[o0 + 2];
        out[b * 32 + o0 + 3] = a3 + lb[o0 + 3];
    }
}

// ---- launch ----------------------------------------------------------------
extern "C" void kernel_launch(void* const* d_in, const int* in_sizes, int n_in,
                              void* d_out, int out_size) {
    const float* x    = (const float*)d_in[0];
    const float* w_in = (const float*)d_in[1];
    const float* w_r  = (const float*)d_in[2];
    const float* lw   = (const float*)d_in[3];
    const float* lb   = (const float*)d_in[4];
    float* out = (float*)d_out;

    cudaFuncSetAttribute(esn_main, cudaFuncAttributeMaxDynamicSharedMemorySize, SMEM_TOTAL);

    prep_zero<<<1, 256>>>();
    prep_w<<<(128 * KC2T * 32 + 255) / 256, 256>>>(w_r, w_in);
    prep_x<<<(int)(((size_t)TT * 16 * 8 * 32) / 256), 256>>>(x);
    esn_main<<<NCTA, THREADS, SMEM_TOTAL>>>();
    readout<<<BB, 256>>>(lw, lb, out);
}

// round 9
// speedup vs baseline: 1.1170x; 1.1170x over previous
#include <cuda_runtime.h>
#include <cuda_fp16.h>

// ---------------------------------------------------------------------------
// ESN recurrence, fp16 tensor-core, round 9.
//  vs R7: 2m x 4n register blocking (8 independent accumulators per kc-iter,
//  2 L1-cyc/mma instead of 3), K split 8 ways (kc = wk + 8i striding, the
//  9th chunk of every warp is its x-chunk -> pre-barrier overlap for all),
//  fp16-packed 8-way K reduction (uint2 per fragment), every warp owns one
//  output fragment. Sync = R7 single-spinner group barrier.
// ---------------------------------------------------------------------------

#define TT     2048
#define BB     256
#define HH     1024
#define DD     128
#define NCTA   128
#define THREADS 512
#define KEEP0  2028
#define NLAST  20
#define KOUT   (NLAST*HH)

#define SMEM_W_BYTES   (72*4*32*16)      // 147456: [kc 72][n8p 4][lane 32] uint4
#define SMEM_RED_BYTES (8*2*8*32*8)      // 32768:  [n8l 8][mi 2][wk 8][lane 32] uint2
#define SMEM_TOTAL     (SMEM_W_BYTES + SMEM_RED_BYTES)

// ---- device globals --------------------------------------------------------
__device__ __align__(16) uint4 g_X[(size_t)TT*16*8*32];   // x frags fp16
__device__ __align__(16) uint4 g_W[16*72*4*32];           // [cta 16][kc 72][n8p 4][lane]
__device__ __align__(16) uint4 g_H[2][16][64][32];        // h frags [buf][m16][kc][lane]
__device__ float    g_hist[(size_t)NLAST*BB*HH];
__device__ unsigned g_gcount[8*32];                       // 8 group counters, 128B apart

// ---- helpers ---------------------------------------------------------------
__device__ __forceinline__ unsigned pkh(float a, float b) {
    __half2 t = __floats2half2_rn(a, b);
    return reinterpret_cast<unsigned&>(t);
}
__device__ __forceinline__ float2 uph(unsigned u) {
    __half2 t = reinterpret_cast<__half2&>(u);
    return __half22float2(t);
}
__device__ __forceinline__ void mma16816(float* c, const uint4 a, const uint2 b) {
    asm volatile(
        "mma.sync.aligned.m16n8k16.row.col.f32.f16.f16.f32 "
        "{%0,%1,%2,%3}, {%4,%5,%6,%7}, {%8,%9}, {%0,%1,%2,%3};\n"
        : "+f"(c[0]), "+f"(c[1]), "+f"(c[2]), "+f"(c[3])
        : "r"(a.x), "r"(a.y), "r"(a.z), "r"(a.w), "r"(b.x), "r"(b.y));
}

// one kc: A frags a0 (m16g0), a1 (m16g1); B uint4 pair b0 (n8 0,1), b1 (n8 2,3)
// c layout: [mi 2][nj 4][4]
__device__ __forceinline__ void mma_kc(float* c, uint4 a0, uint4 a1, uint4 b0, uint4 b1) {
    mma16816(c + 0,  a0, make_uint2(b0.x, b0.y));
    mma16816(c + 4,  a0, make_uint2(b0.z, b0.w));
    mma16816(c + 8,  a0, make_uint2(b1.x, b1.y));
    mma16816(c + 12, a0, make_uint2(b1.z, b1.w));
    mma16816(c + 16, a1, make_uint2(b0.x, b0.y));
    mma16816(c + 20, a1, make_uint2(b0.z, b0.w));
    mma16816(c + 24, a1, make_uint2(b1.x, b1.y));
    mma16816(c + 28, a1, make_uint2(b1.z, b1.w));
}

// ---- prep kernels ----------------------------------------------------------
__global__ void prep_zero() {
    int i = threadIdx.x;
    if (i < 8 * 32) g_gcount[i] = 0u;
}

// g_W[cta][kc][n8p][lane] uint4 = B frags for n8 = cta*8 + n8p*2 + {0,1}
__global__ void prep_w(const float* __restrict__ w_r, const float* __restrict__ w_in) {
    int i = blockIdx.x * blockDim.x + threadIdx.x;
    if (i >= 16 * 72 * 4 * 32) return;
    int lane = i & 31;
    int n8p  = (i >> 5) & 3;
    int kc   = (i >> 7) % 72;
    int cta  = i / (72 * 4 * 32);
    unsigned u[4];
#pragma unroll
    for (int sub = 0; sub < 2; sub++) {
        int n8 = cta * 8 + n8p * 2 + sub;
        int n  = n8 * 8 + (lane >> 2);
        int k0 = kc * 16 + (lane & 3) * 2;
        float v[4];
#pragma unroll
        for (int r = 0; r < 4; r++) {
            int k = k0 + ((r >> 1) * 8) + (r & 1);   // k0,k0+1,k0+8,k0+9
            v[r] = (k < HH) ? w_r[(size_t)k * HH + n] : w_in[(size_t)(k - HH) * HH + n];
        }
        u[2*sub + 0] = pkh(v[0], v[1]);
        u[2*sub + 1] = pkh(v[2], v[3]);
    }
    g_W[i] = make_uint4(u[0], u[1], u[2], u[3]);
}

__global__ void prep_x(const float* __restrict__ x) {
    size_t i = (size_t)blockIdx.x * blockDim.x + threadIdx.x;
    if (i >= (size_t)TT * 16 * 8 * 32) return;
    int lane = (int)(i & 31);
    int kcx  = (int)((i >> 5) & 7);
    int m16  = (int)((i >> 8) & 15);
    int t    = (int)(i >> 12);
    int b = m16 * 16 + (lane >> 2);
    int d = kcx * 16 + (lane & 3) * 2;
    const float* p0 = x + ((size_t)b * TT + t) * DD + d;
    const float* p1 = p0 + (size_t)8 * TT * DD;
    float2 a0 = *(const float2*)(p0);
    float2 a1 = *(const float2*)(p1);
    float2 a2 = *(const float2*)(p0 + 8);
    float2 a3 = *(const float2*)(p1 + 8);
    g_X[i] = make_uint4(pkh(a0.x, a0.y), pkh(a1.x, a1.y),
                        pkh(a2.x, a2.y), pkh(a3.x, a3.y));
}

// ---- main persistent kernel ------------------------------------------------
__global__ void __launch_bounds__(THREADS, 1) esn_main() {
    extern __shared__ __align__(16) unsigned char smem[];
    uint4* sW   = reinterpret_cast<uint4*>(smem);
    uint2* sred = reinterpret_cast<uint2*>(smem + SMEM_W_BYTES);

    const int tid   = threadIdx.x;
    const int lane  = tid & 31;
    const int warp  = tid >> 5;
    const int wn    = warp & 1;          // n-half: n8l 4wn..4wn+3
    const int wk    = warp >> 1;         // K-eighth 0..7 (kc = wk + 8i)
    const int cta_n = blockIdx.x & 15;
    const int cta_m = blockIdx.x >> 4;   // 8 independent groups
    const int m16g0 = 2 * cta_m;
    const int m16g1 = m16g0 + 1;

    // owned output fragment: mi = wk>>2, nj = wk&3, n8l = 4*wn + nj
    const int o_mi  = wk >> 2;
    const int o_nj  = wk & 3;
    const int o_n8l = 4 * wn + o_nj;
    const int o_m16 = m16g0 + o_mi;
    const int o_n8g = cta_n * 8 + o_n8l;
    const int o_kcA = o_n8g >> 1;        // h A-frag chunk
    const int o_half = o_n8l & 1;        // uint2 half within uint4

    // load W tile into smem
    {
        const uint4* src = g_W + (size_t)cta_n * 72 * 4 * 32;
        for (int i = tid; i < 72 * 4 * 32; i += THREADS) sW[i] = src[i];
    }
    __syncthreads();

    float hprev[4];
    unsigned* const cp = &g_gcount[cta_m * 32];

    for (int t = 0; t < TT; t++) {
        float c[32];
#pragma unroll
        for (int i = 0; i < 32; i++) c[i] = 0.f;

        // pre-barrier: own x-chunk (kc = 64 + wk, i.e. kcx = wk)
        {
            uint4 a0 = __ldg(&g_X[(((size_t)t * 16 + m16g0) * 8 + wk) * 32 + lane]);
            uint4 a1 = __ldg(&g_X[(((size_t)t * 16 + m16g1) * 8 + wk) * 32 + lane]);
            int kc = 64 + wk;
            uint4 b0 = sW[(kc * 4 + 2 * wn)     * 32 + lane];
            uint4 b1 = sW[(kc * 4 + 2 * wn + 1) * 32 + lane];
            mma_kc(c, a0, a1, b0, b1);
        }

        if (t > 0) {
            if (tid == 0) {
                unsigned want = (unsigned)t * 16u;
                unsigned v;
                do {
                    asm volatile("ld.acquire.gpu.global.u32 %0, [%1];"
                                 : "=r"(v) : "l"(cp) : "memory");
                } while (v < want);
            }
            __syncthreads();

            const int rb = t & 1;
            const uint4* A0 = &g_H[rb][m16g0][wk][lane];   // stride 8*32 per i
            const uint4* A1 = &g_H[rb][m16g1][wk][lane];
            uint4 ra[2][2];
            ra[0][0] = __ldcg(A0);                 ra[0][1] = __ldcg(A1);
            ra[1][0] = __ldcg(A0 + 8 * 32);        ra[1][1] = __ldcg(A1 + 8 * 32);
#pragma unroll
            for (int i = 0; i < 8; i++) {
                uint4 a0 = ra[i & 1][0];
                uint4 a1 = ra[i & 1][1];
                if (i + 2 < 8) {
                    ra[i & 1][0] = __ldcg(A0 + (size_t)(i + 2) * 8 * 32);
                    ra[i & 1][1] = __ldcg(A1 + (size_t)(i + 2) * 8 * 32);
                }
                int kc = wk + 8 * i;
                uint4 b0 = sW[(kc * 4 + 2 * wn)     * 32 + lane];
                uint4 b1 = sW[(kc * 4 + 2 * wn + 1) * 32 + lane];
                mma_kc(c, a0, a1, b0, b1);
            }
        }

        // write fp16-packed partials for the 7 fragments we don't own
#pragma unroll
        for (int mi = 0; mi < 2; mi++) {
#pragma unroll
            for (int nj = 0; nj < 4; nj++) {
                if (mi == o_mi && nj == o_nj) continue;
                int n8l = 4 * wn + nj;
                const float* p = c + (mi * 16 + nj * 4);
                sred[(((n8l * 2 + mi) * 8) + wk) * 32 + lane] =
                    make_uint2(pkh(p[0], p[1]), pkh(p[2], p[3]));
            }
        }
        __syncthreads();

        // owner epilogue: sum own fp32 partial + 7 foreign fp16 partials
        float fin[4];
        {
            const float* p = c + (o_mi * 16 + o_nj * 4);
            fin[0] = p[0]; fin[1] = p[1]; fin[2] = p[2]; fin[3] = p[3];
            const uint2* rbase = &sred[((o_n8l * 2 + o_mi) * 8) * 32 + lane];
#pragma unroll
            for (int w = 0; w < 8; w++) {
                if (w == wk) continue;
                uint2 v = rbase[w * 32];
                float2 lo = uph(v.x), hi = uph(v.y);
                fin[0] += lo.x; fin[1] += lo.y; fin[2] += hi.x; fin[3] += hi.y;
            }
        }

        float hv[4];
        if (t == 0) {
#pragma unroll
            for (int i = 0; i < 4; i++) hv[i] = tanhf(fin[i]);
        } else {
#pragma unroll
            for (int i = 0; i < 4; i++) hv[i] = 0.1f * hprev[i] + 0.9f * tanhf(fin[i]);
        }
#pragma unroll
        for (int i = 0; i < 4; i++) hprev[i] = hv[i];

        // store h fragment half (uint2) into next-step A-frag layout
        {
            uint2 nh = make_uint2(pkh(hv[0], hv[1]), pkh(hv[2], hv[3]));
            char* dst = (char*)&g_H[(t + 1) & 1][o_m16][o_kcA][lane] + o_half * 8;
            asm volatile("st.global.cg.v2.u32 [%0], {%1, %2};"
                         :: "l"(dst), "r"(nh.x), "r"(nh.y) : "memory");
        }

        // arrive; hist writes after (off critical path)
        if (t < TT - 1) {
            __syncthreads();
            if (tid == 0)
                asm volatile("red.release.gpu.global.add.u32 [%0], %1;"
                             :: "l"(cp), "r"(1u) : "memory");
        }

        if (t >= KEEP0) {
            int r0 = o_m16 * 16 + (lane >> 2);
            int cb = o_n8g * 8 + (lane & 3) * 2;
            size_t base = (size_t)(t - KEEP0) * BB * HH;
            *(float2*)&g_hist[base + (size_t)(r0)     * HH + cb] = make_float2(hv[0], hv[1]);
            *(float2*)&g_hist[base + (size_t)(r0 + 8) * HH + cb] = make_float2(hv[2], hv[3]);
        }
    }
}

// ---- readout ---------------------------------------------------------------
__global__ void readout(const float* __restrict__ lw, const float* __restrict__ lb,
                        float* __restrict__ out) {
    int b    = blockIdx.x;
    int warp = threadIdx.x >> 5;
    int lane = threadIdx.x & 31;
    int o0   = warp * 4;
    float a0 = 0.f, a1 = 0.f, a2 = 0.f, a3 = 0.f;
    for (int k = lane; k < KOUT; k += 32) {
        int s = k >> 10, j = k & (HH - 1);
        float hval = g_hist[(size_t)s * BB * HH + (size_t)b * HH + j];
        a0 += hval * __ldg(&lw[(size_t)(o0 + 0) * KOUT + k]);
        a1 += hval * __ldg(&lw[(size_t)(o0 + 1) * KOUT + k]);
        a2 += hval * __ldg(&lw[(size_t)(o0 + 2) * KOUT + k]);
        a3 += hval * __ldg(&lw[(size_t)(o0 + 3) * KOUT + k]);
    }
#pragma unroll
    for (int off = 16; off > 0; off >>= 1) {
        a0 += __shfl_down_sync(0xffffffffu, a0, off);
        a1 += __shfl_down_sync(0xffffffffu, a1, off);
        a2 += __shfl_down_sync(0xffffffffu, a2, off);
        a3 += __shfl_down_sync(0xffffffffu, a3, off);
    }
    if (lane == 0) {
        out[b * 32 + o0 + 0] = a0 + lb[o0 + 0];
        out[b * 32 + o0 + 1] = a1 + lb[o0 + 1];
        out[b * 32 + o0 + 2] = a2 + lb[o0 + 2];
        out[b * 32 + o0 + 3] = a3 + lb[o0 + 3];
    }
}

// ---- launch ----------------------------------------------------------------
extern "C" void kernel_launch(void* const* d_in, const int* in_sizes, int n_in,
                              void* d_out, int out_size) {
    const float* x    = (const float*)d_in[0];
    const float* w_in = (const float*)d_in[1];
    const float* w_r  = (const float*)d_in[2];
    const float* lw   = (const float*)d_in[3];
    const float* lb   = (const float*)d_in[4];
    float* out = (float*)d_out;

    cudaFuncSetAttribute(esn_main, cudaFuncAttributeMaxDynamicSharedMemorySize, SMEM_TOTAL);

    prep_zero<<<1, 256>>>();
    prep_w<<<(16 * 72 * 4 * 32 + 255) / 256, 256>>>(w_r, w_in);
    prep_x<<<(int)(((size_t)TT * 16 * 8 * 32) / 256), 256>>>(x);
    esn_main<<<NCTA, THREADS, SMEM_TOTAL>>>();
    readout<<<BB, 256>>>(lw, lb, out);
}